// round 3
// baseline (speedup 1.0000x reference)
#include <cuda_runtime.h>
#include <cuda_bf16.h>
#include <cstdint>

// -------------------------------------------------------------------------
// CoralFocalLoss_MultiTask, single fused kernel, 4 samples per thread.
//
// Per element (logit x, binary coral target tm):
//   loss = alpha(tm) * h(y),  y = tm ? x : -x,  alpha = tm ? 0.25 : 0.75
//   h(y) = sigmoid(-y)^2 * softplus(-y) = u^2 * (s - y)
//      t = e^y, u = 1/(1+t), s = log(1+t)
// Row loss scaled by class_weights[kl_t]. Outputs are means.
//
// 4-sample granularity makes every stream a whole number of 16B vectors:
//   kl: 4x float4, jsnm: 3x float4, jsnl: 3x float4, targets: 3x int4
// => 13 coalesced LDG.128 per thread, front-batched for MLP.
// __launch_bounds__(256,3) gives ptxas ~85 regs to keep them all live.
//
// Finalization fused: last block (threadfence-reduction ticket) sums
// per-block partials in fixed order (deterministic) and writes d_out.
// -------------------------------------------------------------------------

#define NTHREADS 256
#define MAXBLOCKS 4096

__device__ float        g_partials[MAXBLOCKS * 3];
__device__ unsigned int g_ticket = 0;   // wraps back to 0 every launch

__device__ __forceinline__ float fast_rcp(float a) {
    // a = 1 + e^y >= 1; bit trick + 2 Newton iterations (~6e-6 rel err)
    float u = __int_as_float(0x7EF311C3 - __float_as_int(a));
    u = u * (2.0f - a * u);
    u = u * (2.0f - a * u);
    return u;
}

__device__ __forceinline__ float coral_term(float x, bool tm) {
    float y     = tm ? x : -x;
    float alpha = tm ? 0.25f : 0.75f;
    float t = __expf(y);           // MUFU EX2 (+mul)
    float a = 1.0f + t;
    float u = fast_rcp(a);         // FMA pipe
    float s = __logf(a);           // MUFU LG2 (+mul)
    return alpha * (u * u) * (s - y);
}

// one sample's 10-logit contribution, given its row data
__device__ __forceinline__ void sample_accum(
    float4 q, float m0, float m1, float m2, float l0, float l1, float l2,
    int kt, int mt, int lt, float w,
    float& sum_kl, float& sum_m, float& sum_l)
{
    float rk = coral_term(q.x, 0 < kt) + coral_term(q.y, 1 < kt)
             + coral_term(q.z, 2 < kt) + coral_term(q.w, 3 < kt);
    sum_kl += w * rk;
    float rm = coral_term(m0, 0 < mt) + coral_term(m1, 1 < mt)
             + coral_term(m2, 2 < mt);
    sum_m += w * rm;
    float rl = coral_term(l0, 0 < lt) + coral_term(l1, 1 < lt)
             + coral_term(l2, 2 < lt);
    sum_l += w * rl;
}

__global__ void __launch_bounds__(NTHREADS, 3)
coral_fused_kernel(const float* __restrict__ kl_logits,
                   const float* __restrict__ jsnm_logits,
                   const float* __restrict__ jsnl_logits,
                   const float* __restrict__ class_weights,
                   const int*   __restrict__ kl_t,
                   const int*   __restrict__ jsnm_t,
                   const int*   __restrict__ jsnl_t,
                   float* __restrict__ out,
                   int n)
{
    __shared__ float s_w[5];
    __shared__ bool  s_is_last;
    if (threadIdx.x < 5) s_w[threadIdx.x] = class_weights[threadIdx.x];
    __syncthreads();

    float sum_kl = 0.0f, sum_m = 0.0f, sum_l = 0.0f;

    const int ntasks = n >> 2;                       // 4 samples per task
    const int g = blockIdx.x * NTHREADS + threadIdx.x;

    if (g < ntasks) {
        // ---- front-batched loads: 13 x LDG.128, all coalesced ----
        const float4* kq = reinterpret_cast<const float4*>(kl_logits)   + 4 * (size_t)g;
        const float4* mq = reinterpret_cast<const float4*>(jsnm_logits) + 3 * (size_t)g;
        const float4* lq = reinterpret_cast<const float4*>(jsnl_logits) + 3 * (size_t)g;

        float4 k0 = kq[0], k1 = kq[1], k2 = kq[2], k3 = kq[3];
        float4 m0 = mq[0], m1 = mq[1], m2 = mq[2];
        float4 l0 = lq[0], l1 = lq[1], l2 = lq[2];
        int4 kt = reinterpret_cast<const int4*>(kl_t)[g];
        int4 mt = reinterpret_cast<const int4*>(jsnm_t)[g];
        int4 lt = reinterpret_cast<const int4*>(jsnl_t)[g];

        float w0 = s_w[kt.x], w1 = s_w[kt.y], w2 = s_w[kt.z], w3 = s_w[kt.w];

        // sample 0: jsnm floats 0,1,2 ; jsnl floats 0,1,2
        sample_accum(k0, m0.x, m0.y, m0.z, l0.x, l0.y, l0.z,
                     kt.x, mt.x, lt.x, w0, sum_kl, sum_m, sum_l);
        // sample 1: floats 3,4,5
        sample_accum(k1, m0.w, m1.x, m1.y, l0.w, l1.x, l1.y,
                     kt.y, mt.y, lt.y, w1, sum_kl, sum_m, sum_l);
        // sample 2: floats 6,7,8
        sample_accum(k2, m1.z, m1.w, m2.x, l1.z, l1.w, l2.x,
                     kt.z, mt.z, lt.z, w2, sum_kl, sum_m, sum_l);
        // sample 3: floats 9,10,11
        sample_accum(k3, m2.y, m2.z, m2.w, l2.y, l2.z, l2.w,
                     kt.w, mt.w, lt.w, w3, sum_kl, sum_m, sum_l);
    }

    // tail: n % 4 leftovers (none for this problem, kept for correctness)
    if ((n & 3) && blockIdx.x == 0 && threadIdx.x == 0) {
        for (int i = ntasks * 4; i < n; i++) {
            int kt = kl_t[i], mt = jsnm_t[i], lt = jsnl_t[i];
            float w = s_w[kt];
            const float* q = kl_logits + 4 * (size_t)i;
            sum_kl += w * (coral_term(q[0], 0 < kt) + coral_term(q[1], 1 < kt)
                         + coral_term(q[2], 2 < kt) + coral_term(q[3], 3 < kt));
            const float* pm = jsnm_logits + 3 * (size_t)i;
            sum_m  += w * (coral_term(pm[0], 0 < mt) + coral_term(pm[1], 1 < mt)
                         + coral_term(pm[2], 2 < mt));
            const float* pl = jsnl_logits + 3 * (size_t)i;
            sum_l  += w * (coral_term(pl[0], 0 < lt) + coral_term(pl[1], 1 < lt)
                         + coral_term(pl[2], 2 < lt));
        }
    }

    // -------- block reduction (deterministic) --------
    const unsigned FULL = 0xFFFFFFFFu;
    #pragma unroll
    for (int o = 16; o > 0; o >>= 1) {
        sum_kl += __shfl_down_sync(FULL, sum_kl, o);
        sum_m  += __shfl_down_sync(FULL, sum_m,  o);
        sum_l  += __shfl_down_sync(FULL, sum_l,  o);
    }

    __shared__ float s_red[3][NTHREADS / 32];
    int wid = threadIdx.x >> 5;
    int lid = threadIdx.x & 31;
    if (lid == 0) {
        s_red[0][wid] = sum_kl;
        s_red[1][wid] = sum_m;
        s_red[2][wid] = sum_l;
    }
    __syncthreads();

    if (threadIdx.x == 0) {
        float v0 = 0.0f, v1 = 0.0f, v2 = 0.0f;
        #pragma unroll
        for (int i = 0; i < NTHREADS / 32; i++) {
            v0 += s_red[0][i];
            v1 += s_red[1][i];
            v2 += s_red[2][i];
        }
        g_partials[blockIdx.x * 3 + 0] = v0;
        g_partials[blockIdx.x * 3 + 1] = v1;
        g_partials[blockIdx.x * 3 + 2] = v2;
        __threadfence();
        unsigned t = atomicInc(&g_ticket, gridDim.x - 1);
        s_is_last = (t == gridDim.x - 1);
    }
    __syncthreads();

    // -------- last block finalizes --------
    if (s_is_last) {
        int nb = gridDim.x;
        float v0 = 0.0f, v1 = 0.0f, v2 = 0.0f;
        for (int i = threadIdx.x; i < nb; i += NTHREADS) {
            v0 += g_partials[i * 3 + 0];
            v1 += g_partials[i * 3 + 1];
            v2 += g_partials[i * 3 + 2];
        }
        #pragma unroll
        for (int o = 16; o > 0; o >>= 1) {
            v0 += __shfl_down_sync(FULL, v0, o);
            v1 += __shfl_down_sync(FULL, v1, o);
            v2 += __shfl_down_sync(FULL, v2, o);
        }
        if (lid == 0) {
            s_red[0][wid] = v0;
            s_red[1][wid] = v1;
            s_red[2][wid] = v2;
        }
        __syncthreads();
        if (threadIdx.x == 0) {
            float t0 = 0.0f, t1 = 0.0f, t2 = 0.0f;
            #pragma unroll
            for (int i = 0; i < NTHREADS / 32; i++) {
                t0 += s_red[0][i];
                t1 += s_red[1][i];
                t2 += s_red[2][i];
            }
            float fn = (float)n;
            float l_kl   = t0 / (4.0f * fn);
            float l_jsnm = t1 / (3.0f * fn);
            float l_jsnl = t2 / (3.0f * fn);
            out[0] = (l_kl + l_jsnm + l_jsnl) * (1.0f / 3.0f);
            out[1] = l_kl;
            out[2] = l_jsnm;
            out[3] = l_jsnl;
        }
    }
}

extern "C" void kernel_launch(void* const* d_in, const int* in_sizes, int n_in,
                              void* d_out, int out_size)
{
    const float* kl_logits     = (const float*)d_in[0];
    const float* jsnm_logits   = (const float*)d_in[1];
    const float* jsnl_logits   = (const float*)d_in[2];
    const float* class_weights = (const float*)d_in[3];
    const int*   kl_t          = (const int*)d_in[4];
    const int*   jsnm_t        = (const int*)d_in[5];
    const int*   jsnl_t        = (const int*)d_in[6];

    int n = in_sizes[4];  // N samples (kl_t element count)

    int ntasks = n >> 2;
    int grid = (ntasks + NTHREADS - 1) / NTHREADS;
    if (grid < 1) grid = 1;
    if (grid > MAXBLOCKS) grid = MAXBLOCKS;   // n <= 4.19e6 holds for this problem

    coral_fused_kernel<<<grid, NTHREADS>>>(
        kl_logits, jsnm_logits, jsnl_logits, class_weights,
        kl_t, jsnm_t, jsnl_t, (float*)d_out, n);
}

// round 4
// speedup vs baseline: 1.0541x; 1.0541x over previous
#include <cuda_runtime.h>
#include <cuda_bf16.h>
#include <cstdint>

// -------------------------------------------------------------------------
// CoralFocalLoss_MultiTask — R1 main-loop body (best measured: 19.6us)
// + fused last-block finalize (removes 5.8us separate-kernel tail).
//
// Per element (logit x, binary coral target tm):
//   loss = alpha(tm) * h(y),  y = tm ? x : -x,  alpha = tm ? 0.25 : 0.75
//   h(y) = sigmoid(-y)^2 * softplus(-y) = u^2 * (s - y)
//      t = e^y, u = 1/(1+t), s = log(1+t)
// Row loss scaled by class_weights[kl_t]. Outputs are means.
//
// 2 MUFU (EX2, LG2) per logit; reciprocal on the FMA pipe (bit trick +
// 2 Newton steps, ~6e-6 one-sided rel err).
//
// Grid = 1184 blocks x 256 thr = exactly one full-occupancy wave on 148 SMs
// (8 blocks/SM at 32 regs). Cross-warp parallelism covers DRAM latency;
// per-thread body stays simple to keep regs at 32.
// -------------------------------------------------------------------------

#define NBLOCKS 1184
#define NTHREADS 256

__device__ float        g_partials[NBLOCKS * 3];
__device__ unsigned int g_ticket = 0;   // atomicInc wraps to 0 each launch

__device__ __forceinline__ float fast_rcp(float a) {
    // a = 1 + e^y >= 1; bit trick + 2 Newton iterations (~6e-6 rel err)
    float u = __int_as_float(0x7EF311C3 - __float_as_int(a));
    u = u * (2.0f - a * u);
    u = u * (2.0f - a * u);
    return u;
}

__device__ __forceinline__ float coral_term(float x, bool tm) {
    float y     = tm ? x : -x;
    float alpha = tm ? 0.25f : 0.75f;
    float t = __expf(y);           // MUFU EX2 (+mul)
    float a = 1.0f + t;
    float u = fast_rcp(a);         // FMA pipe
    float s = __logf(a);           // MUFU LG2 (+mul)
    return alpha * (u * u) * (s - y);
}

__global__ void __launch_bounds__(NTHREADS)
coral_fused_kernel(const float* __restrict__ kl_logits,
                   const float* __restrict__ jsnm_logits,
                   const float* __restrict__ jsnl_logits,
                   const float* __restrict__ class_weights,
                   const int*   __restrict__ kl_t,
                   const int*   __restrict__ jsnm_t,
                   const int*   __restrict__ jsnl_t,
                   float* __restrict__ out,
                   int n)
{
    __shared__ float s_w[5];
    __shared__ bool  s_is_last;
    if (threadIdx.x < 5) s_w[threadIdx.x] = class_weights[threadIdx.x];
    __syncthreads();

    float sum_kl = 0.0f, sum_m = 0.0f, sum_l = 0.0f;

    const int stride = gridDim.x * blockDim.x;
    for (int i = blockIdx.x * blockDim.x + threadIdx.x; i < n; i += stride) {
        int kt = kl_t[i];
        int mt = jsnm_t[i];
        int lt = jsnl_t[i];
        float w = s_w[kt];

        float4 q = reinterpret_cast<const float4*>(kl_logits)[i];
        float rk = coral_term(q.x, 0 < kt)
                 + coral_term(q.y, 1 < kt)
                 + coral_term(q.z, 2 < kt)
                 + coral_term(q.w, 3 < kt);
        sum_kl += w * rk;

        const float* pm = jsnm_logits + 3 * (size_t)i;
        float rm = coral_term(pm[0], 0 < mt)
                 + coral_term(pm[1], 1 < mt)
                 + coral_term(pm[2], 2 < mt);
        sum_m += w * rm;

        const float* pl = jsnl_logits + 3 * (size_t)i;
        float rl = coral_term(pl[0], 0 < lt)
                 + coral_term(pl[1], 1 < lt)
                 + coral_term(pl[2], 2 < lt);
        sum_l += w * rl;
    }

    // -------- block reduction (deterministic) --------
    const unsigned FULL = 0xFFFFFFFFu;
    #pragma unroll
    for (int o = 16; o > 0; o >>= 1) {
        sum_kl += __shfl_down_sync(FULL, sum_kl, o);
        sum_m  += __shfl_down_sync(FULL, sum_m,  o);
        sum_l  += __shfl_down_sync(FULL, sum_l,  o);
    }

    __shared__ float s_red[3][NTHREADS / 32];
    int wid = threadIdx.x >> 5;
    int lid = threadIdx.x & 31;
    if (lid == 0) {
        s_red[0][wid] = sum_kl;
        s_red[1][wid] = sum_m;
        s_red[2][wid] = sum_l;
    }
    __syncthreads();

    if (threadIdx.x == 0) {
        float v0 = 0.0f, v1 = 0.0f, v2 = 0.0f;
        #pragma unroll
        for (int i = 0; i < NTHREADS / 32; i++) {
            v0 += s_red[0][i];
            v1 += s_red[1][i];
            v2 += s_red[2][i];
        }
        g_partials[blockIdx.x * 3 + 0] = v0;
        g_partials[blockIdx.x * 3 + 1] = v1;
        g_partials[blockIdx.x * 3 + 2] = v2;
        __threadfence();
        unsigned t = atomicInc(&g_ticket, gridDim.x - 1);
        s_is_last = (t == gridDim.x - 1);
    }
    __syncthreads();

    // -------- last block to arrive finalizes (fixed-order, deterministic) --------
    if (s_is_last) {
        float v0 = 0.0f, v1 = 0.0f, v2 = 0.0f;
        for (int i = threadIdx.x; i < NBLOCKS; i += NTHREADS) {
            v0 += g_partials[i * 3 + 0];
            v1 += g_partials[i * 3 + 1];
            v2 += g_partials[i * 3 + 2];
        }
        #pragma unroll
        for (int o = 16; o > 0; o >>= 1) {
            v0 += __shfl_down_sync(FULL, v0, o);
            v1 += __shfl_down_sync(FULL, v1, o);
            v2 += __shfl_down_sync(FULL, v2, o);
        }
        if (lid == 0) {
            s_red[0][wid] = v0;
            s_red[1][wid] = v1;
            s_red[2][wid] = v2;
        }
        __syncthreads();
        if (threadIdx.x == 0) {
            float t0 = 0.0f, t1 = 0.0f, t2 = 0.0f;
            #pragma unroll
            for (int i = 0; i < NTHREADS / 32; i++) {
                t0 += s_red[0][i];
                t1 += s_red[1][i];
                t2 += s_red[2][i];
            }
            float fn = (float)n;
            float l_kl   = t0 / (4.0f * fn);
            float l_jsnm = t1 / (3.0f * fn);
            float l_jsnl = t2 / (3.0f * fn);
            out[0] = (l_kl + l_jsnm + l_jsnl) * (1.0f / 3.0f);
            out[1] = l_kl;
            out[2] = l_jsnm;
            out[3] = l_jsnl;
        }
    }
}

extern "C" void kernel_launch(void* const* d_in, const int* in_sizes, int n_in,
                              void* d_out, int out_size)
{
    const float* kl_logits     = (const float*)d_in[0];
    const float* jsnm_logits   = (const float*)d_in[1];
    const float* jsnl_logits   = (const float*)d_in[2];
    const float* class_weights = (const float*)d_in[3];
    const int*   kl_t          = (const int*)d_in[4];
    const int*   jsnm_t        = (const int*)d_in[5];
    const int*   jsnl_t        = (const int*)d_in[6];

    int n = in_sizes[4];  // N samples (kl_t element count)

    coral_fused_kernel<<<NBLOCKS, NTHREADS>>>(
        kl_logits, jsnm_logits, jsnl_logits, class_weights,
        kl_t, jsnm_t, jsnl_t, (float*)d_out, n);
}